// round 4
// baseline (speedup 1.0000x reference)
#include <cuda_runtime.h>
#include <math.h>

// Problem constants (validated against in_sizes at launch).
#define NMAX 20000
#define EMAX 640000
#define ETOTMAX (EMAX + NMAX)

// ---------------- device scratch (no allocations allowed) ----------------
__device__ int   g_is64;
__device__ int   g_src[EMAX];
__device__ int   g_dst[EMAX];
__device__ float g_easum[NMAX];
__device__ float g_degf[NMAX];
__device__ float g_ealoop[NMAX];
__device__ int   g_cnt[NMAX];
__device__ int   g_cursor[NMAX];
__device__ int   g_off[NMAX + 1];
__device__ int   g_eid[ETOTMAX];
__device__ float g_xl1[NMAX * 256];
__device__ float g_xr1[NMAX * 256];
__device__ float g_h1[NMAX * 256];
__device__ float g_xl2[NMAX * 128];
__device__ float g_xr2[NMAX * 128];
__device__ float g_s1[(size_t)ETOTMAX * 8];
__device__ float g_s2[ETOTMAX];
__device__ float g_pool[128];

// Device-side scratch selector (avoids any host-side symbol queries).
__device__ __forceinline__ float* buf_sel(int code) {
    switch (code) {
        case 0:  return g_xl1;
        case 1:  return g_xr1;
        case 2:  return g_h1;
        case 3:  return g_xl2;
        default: return g_xr2;
    }
}

// ---------------- init (graph replays reuse accumulators) ----------------
__global__ void init_kernel(int n) {
    int i = blockIdx.x * blockDim.x + threadIdx.x;
    if (i < n) {
        g_easum[i]  = 0.f;
        g_degf[i]   = 0.f;
        g_cursor[i] = 0;
        g_cnt[i]    = 1;   // self-loop pre-counted
    }
    if (i < 128) g_pool[i] = 0.f;
}

// Detect whether edge_index is stored as int64 (little-endian: high words 0)
__global__ void detect_kernel(const int* __restrict__ raw) {
    int nz = 0;
    for (int i = threadIdx.x; i < 64; i += 32)
        if (raw[2 * i + 1] != 0) nz = 1;
    nz = __any_sync(0xffffffffu, nz);
    if (threadIdx.x == 0) g_is64 = nz ? 0 : 1;
}

// Extract src/dst, accumulate per-dst edge_attr sum / degree / CSR counts
__global__ void extract_kernel(const int* __restrict__ raw,
                               const float* __restrict__ ea, int E) {
    int e = blockIdx.x * blockDim.x + threadIdx.x;
    if (e >= E) return;
    int is64 = g_is64;
    int s = is64 ? raw[2 * e]       : raw[e];
    int d = is64 ? raw[2 * (E + e)] : raw[E + e];
    g_src[e] = s;
    g_dst[e] = d;
    atomicAdd(&g_easum[d], ea[e]);
    atomicAdd(&g_degf[d], 1.0f);
    atomicAdd(&g_cnt[d], 1);
}

__global__ void ealoop_kernel(int n) {
    int i = blockIdx.x * blockDim.x + threadIdx.x;
    if (i < n) g_ealoop[i] = g_easum[i] / fmaxf(g_degf[i], 1.0f);
}

// Single-block exclusive prefix sum over g_cnt -> g_off
__global__ void scan_kernel(int n) {
    __shared__ int sh[1024];
    __shared__ int carry;
    int tid = threadIdx.x;
    if (tid == 0) carry = 0;
    __syncthreads();
    for (int base = 0; base < n; base += 1024) {
        int i = base + tid;
        int v = (i < n) ? g_cnt[i] : 0;
        sh[tid] = v;
        __syncthreads();
        for (int o = 1; o < 1024; o <<= 1) {
            int t = (tid >= o) ? sh[tid - o] : 0;
            __syncthreads();
            sh[tid] += t;
            __syncthreads();
        }
        if (i < n) g_off[i] = carry + sh[tid] - v;
        __syncthreads();
        if (tid == 0) carry += sh[1023];
        __syncthreads();
    }
    if (tid == 0) g_off[n] = carry;
}

// Fill CSR edge-id lists (edge k<E: real edge; k>=E: self loop of node k-E)
__global__ void scatter_kernel(int E, int n) {
    int k = blockIdx.x * blockDim.x + threadIdx.x;
    int tot = E + n;
    if (k >= tot) return;
    int d = (k < E) ? g_dst[k] : (k - E);
    int pos = g_off[d] + atomicAdd(&g_cursor[d], 1);
    g_eid[pos] = k;
}

// ------- fp32 GEMM with bias, dual-weight: z selects (Wl,bl,Cl)/(Wr,br,Cr)
__global__ void gemm_bias_dual(const float* __restrict__ Ain, int Acode,
                               const float* __restrict__ W0, const float* __restrict__ b0, int C0code,
                               const float* __restrict__ W1, const float* __restrict__ b1, int C1code,
                               int M, int K, int Nn) {
    const float* A = (Acode >= 0) ? buf_sel(Acode) : Ain;
    const float* W    = (blockIdx.z == 0) ? W0 : W1;
    const float* bias = (blockIdx.z == 0) ? b0 : b1;
    float* C = buf_sel(blockIdx.z == 0 ? C0code : C1code);

    __shared__ float As[16][65];
    __shared__ float Bs[16][64];
    const int tid = threadIdx.x;
    const int tx = tid & 15, ty = tid >> 4;
    const int row0 = blockIdx.x * 64, col0 = blockIdx.y * 64;
    float acc[4][4] = {};
    for (int k0 = 0; k0 < K; k0 += 16) {
        #pragma unroll
        for (int i = 0; i < 4; i++) {
            int li = tid + i * 256;
            int r = li >> 4, c = li & 15;
            int gr = row0 + r;
            As[c][r] = (gr < M) ? A[gr * K + k0 + c] : 0.f;
        }
        #pragma unroll
        for (int i = 0; i < 4; i++) {
            int li = tid + i * 256;
            int r = li >> 6, c = li & 63;
            Bs[r][c] = W[(k0 + r) * Nn + col0 + c];
        }
        __syncthreads();
        #pragma unroll
        for (int kk = 0; kk < 16; kk++) {
            float a[4], b[4];
            #pragma unroll
            for (int i = 0; i < 4; i++) a[i] = As[kk][ty * 4 + i];
            #pragma unroll
            for (int i = 0; i < 4; i++) b[i] = Bs[kk][tx * 4 + i];
            #pragma unroll
            for (int i = 0; i < 4; i++)
                #pragma unroll
                for (int j = 0; j < 4; j++) acc[i][j] += a[i] * b[j];
        }
        __syncthreads();
    }
    #pragma unroll
    for (int i = 0; i < 4; i++) {
        int gr = row0 + ty * 4 + i;
        if (gr >= M) continue;
        #pragma unroll
        for (int j = 0; j < 4; j++) {
            int gc = col0 + tx * 4 + j;
            C[gr * Nn + gc] = acc[i][j] + bias[gc];
        }
    }
}

// ---------------- layer 1 scores (H=8, C=32), one warp per CSR slot ------
__global__ void score1_kernel(const float* __restrict__ We,
                              const float* __restrict__ att,
                              const float* __restrict__ ea, int E, int Etot) {
    __shared__ float Wsh[256], Ash[256];
    int t = threadIdx.x;
    Wsh[t] = We[t];
    Ash[t] = att[t];
    __syncthreads();
    int warp = t >> 5, lane = t & 31;
    int p = blockIdx.x * 8 + warp;
    if (p >= Etot) return;
    int k = g_eid[p];
    int s, d;
    float eav;
    if (k < E) { s = g_src[k]; d = g_dst[k]; eav = ea[k]; }
    else       { s = d = k - E; eav = g_ealoop[s]; }
    const float* xl = g_xl1 + (size_t)s * 256;
    const float* xr = g_xr1 + (size_t)d * 256;
    #pragma unroll
    for (int h = 0; h < 8; h++) {
        int c = h * 32 + lane;
        float m = xl[c] + xr[c] + eav * Wsh[c];
        m = (m > 0.f) ? m : 0.2f * m;
        float v = m * Ash[c];
        #pragma unroll
        for (int o = 16; o; o >>= 1) v += __shfl_xor_sync(0xffffffffu, v, o);
        if (lane == 0) g_s1[(size_t)p * 8 + h] = v;
    }
}

// ---------------- layer 2 scores (H=1, C=128) ----------------------------
__global__ void score2_kernel(const float* __restrict__ We,
                              const float* __restrict__ att,
                              const float* __restrict__ ea, int E, int Etot) {
    __shared__ float Wsh[128], Ash[128];
    int t = threadIdx.x;
    if (t < 128) { Wsh[t] = We[t]; Ash[t] = att[t]; }
    __syncthreads();
    int warp = t >> 5, lane = t & 31;
    int p = blockIdx.x * 8 + warp;
    if (p >= Etot) return;
    int k = g_eid[p];
    int s, d;
    float eav;
    if (k < E) { s = g_src[k]; d = g_dst[k]; eav = ea[k]; }
    else       { s = d = k - E; eav = g_ealoop[s]; }
    const float* xl = g_xl2 + (size_t)s * 128;
    const float* xr = g_xr2 + (size_t)d * 128;
    float acc = 0.f;
    #pragma unroll
    for (int i = 0; i < 4; i++) {
        int c = lane + 32 * i;
        float m = xl[c] + xr[c] + eav * Wsh[c];
        m = (m > 0.f) ? m : 0.2f * m;
        acc += m * Ash[c];
    }
    #pragma unroll
    for (int o = 16; o; o >>= 1) acc += __shfl_xor_sync(0xffffffffu, acc, o);
    if (lane == 0) g_s2[p] = acc;
}

// ---------- layer 1 aggregation: one block (256 thr) per node ------------
__global__ void agg1_kernel(const float* __restrict__ bias, int E) {
    const int CH = 64;
    __shared__ float mx[8], idn[8];
    __shared__ float ash[CH * 8];
    __shared__ int   ssh[CH];
    int j = blockIdx.x;
    int off = g_off[j], end = g_off[j + 1];
    int d = end - off;
    int t = threadIdx.x;
    int h = t >> 5, lane = t & 31;

    // online softmax stats per head (warp h owns head h)
    float m = -1e30f, sum = 0.f;
    for (int idx = lane; idx < d; idx += 32) {
        float sv = g_s1[(size_t)(off + idx) * 8 + h];
        if (sv > m) { sum = sum * __expf(m - sv) + 1.0f; sum = sum; m = sv; }
        else        { sum += __expf(sv - m); }
    }
    #pragma unroll
    for (int o = 16; o; o >>= 1) {
        float m2 = __shfl_xor_sync(0xffffffffu, m, o);
        float s2 = __shfl_xor_sync(0xffffffffu, sum, o);
        float nm = fmaxf(m, m2);
        sum = sum * __expf(m - nm) + s2 * __expf(m2 - nm);
        m = nm;
    }
    if (lane == 0) { mx[h] = m; idn[h] = 1.0f / (sum + 1e-16f); }
    __syncthreads();

    float accv = 0.f;
    for (int cs = 0; cs < d; cs += CH) {
        int cl = min(CH, d - cs);
        for (int i = t; i < cl * 8; i += 256) {
            float sv = g_s1[(size_t)(off + cs) * 8 + i];
            int hh = i & 7;
            ash[i] = __expf(sv - mx[hh]) * idn[hh];
        }
        for (int i = t; i < cl; i += 256) {
            int k = g_eid[off + cs + i];
            ssh[i] = (k < E) ? g_src[k] : (k - E);
        }
        __syncthreads();
        #pragma unroll 4
        for (int el = 0; el < cl; el++) {
            float a = ash[el * 8 + h];
            accv += a * g_xl1[(size_t)ssh[el] * 256 + h * 32 + lane];
        }
        __syncthreads();
    }
    int c = h * 32 + lane;
    g_h1[(size_t)j * 256 + c] = fmaxf(accv + bias[c], 0.f);
}

// ---------- layer 2 aggregation + mean pool: block (128 thr) per node ----
__global__ void agg2_kernel(const float* __restrict__ bias, int E) {
    __shared__ float wm[4], ws[4];
    __shared__ float M0sh, IVsh;
    __shared__ float ash[128];
    __shared__ int   ssh[128];
    int j = blockIdx.x;
    int off = g_off[j], end = g_off[j + 1];
    int d = end - off;
    int t = threadIdx.x;
    int w = t >> 5, lane = t & 31;

    float m = -1e30f, sum = 0.f;
    for (int idx = t; idx < d; idx += 128) {
        float sv = g_s2[off + idx];
        if (sv > m) { sum = sum * __expf(m - sv) + 1.0f; m = sv; }
        else        { sum += __expf(sv - m); }
    }
    #pragma unroll
    for (int o = 16; o; o >>= 1) {
        float m2 = __shfl_xor_sync(0xffffffffu, m, o);
        float s2 = __shfl_xor_sync(0xffffffffu, sum, o);
        float nm = fmaxf(m, m2);
        sum = sum * __expf(m - nm) + s2 * __expf(m2 - nm);
        m = nm;
    }
    if (lane == 0) { wm[w] = m; ws[w] = sum; }
    __syncthreads();
    if (t == 0) {
        float M0 = fmaxf(fmaxf(wm[0], wm[1]), fmaxf(wm[2], wm[3]));
        float S0 = ws[0] * __expf(wm[0] - M0) + ws[1] * __expf(wm[1] - M0)
                 + ws[2] * __expf(wm[2] - M0) + ws[3] * __expf(wm[3] - M0);
        M0sh = M0;
        IVsh = 1.0f / (S0 + 1e-16f);
    }
    __syncthreads();
    float M0 = M0sh, invd = IVsh;

    float accv = 0.f;
    for (int cs = 0; cs < d; cs += 128) {
        int cl = min(128, d - cs);
        if (t < cl) {
            ash[t] = __expf(g_s2[off + cs + t] - M0) * invd;
            int k = g_eid[off + cs + t];
            ssh[t] = (k < E) ? g_src[k] : (k - E);
        }
        __syncthreads();
        #pragma unroll 4
        for (int el = 0; el < cl; el++)
            accv += ash[el] * g_xl2[(size_t)ssh[el] * 128 + t];
        __syncthreads();
    }
    float val = fmaxf(accv + bias[t], 0.f);
    atomicAdd(&g_pool[t], val);
}

// ---------------- final: mean, softmax, sigmoid(alpha) -------------------
__global__ void final_kernel(const float* __restrict__ alpha_in,
                             float* __restrict__ out, int out_size, float invN) {
    __shared__ float sh[128];
    int t = threadIdx.x;
    float v = g_pool[t] * invN;
    sh[t] = v;
    __syncthreads();
    for (int o = 64; o; o >>= 1) {
        if (t < o) sh[t] = fmaxf(sh[t], sh[t + o]);
        __syncthreads();
    }
    float mx = sh[0];
    __syncthreads();
    float e = __expf(v - mx);
    sh[t] = e;
    __syncthreads();
    for (int o = 64; o; o >>= 1) {
        if (t < o) sh[t] += sh[t + o];
        __syncthreads();
    }
    float s = sh[0];
    out[t] = e / s;
    if (t == 0 && out_size > 128)
        out[128] = 1.0f / (1.0f + __expf(-alpha_in[0]));
}

// -------------------------------------------------------------------------
extern "C" void kernel_launch(void* const* d_in, const int* in_sizes, int n_in,
                              void* d_out, int out_size) {
    (void)n_in;
    const float* x     = (const float*)d_in[0];
    const int*   eidx  = (const int*)d_in[1];   // int32 or int64 (detected)
    const float* ea    = (const float*)d_in[2];
    const float* W1l   = (const float*)d_in[3];
    const float* b1l   = (const float*)d_in[4];
    const float* W1r   = (const float*)d_in[5];
    const float* b1r   = (const float*)d_in[6];
    const float* We1   = (const float*)d_in[7];
    const float* att1  = (const float*)d_in[8];
    const float* bias1 = (const float*)d_in[9];
    const float* W2l   = (const float*)d_in[10];
    const float* b2l   = (const float*)d_in[11];
    const float* W2r   = (const float*)d_in[12];
    const float* b2r   = (const float*)d_in[13];
    const float* We2   = (const float*)d_in[14];
    const float* att2  = (const float*)d_in[15];
    const float* bias2 = (const float*)d_in[16];
    const float* alpha = (const float*)d_in[17];
    float* out = (float*)d_out;

    int N = in_sizes[0] / 128;
    if (N > NMAX) N = NMAX;
    int E = in_sizes[1] / 2;
    if (E > EMAX) E = EMAX;
    int Etot = E + N;

    // graph preprocessing
    init_kernel<<<(N + 255) / 256, 256>>>(N);
    detect_kernel<<<1, 32>>>(eidx);
    extract_kernel<<<(E + 255) / 256, 256>>>(eidx, ea, E);
    ealoop_kernel<<<(N + 255) / 256, 256>>>(N);
    scan_kernel<<<1, 1024>>>(N);
    scatter_kernel<<<(Etot + 255) / 256, 256>>>(E, N);

    int mb = (N + 63) / 64;

    // layer 1: xl1 = x@W1l+b1l, xr1 = x@W1r+b1r (one dual launch)
    gemm_bias_dual<<<dim3(mb, 4, 2), 256>>>(x, -1, W1l, b1l, 0, W1r, b1r, 1,
                                            N, 128, 256);
    score1_kernel<<<(Etot + 7) / 8, 256>>>(We1, att1, ea, E, Etot);
    agg1_kernel<<<N, 256>>>(bias1, E);

    // layer 2: xl2 = h1@W2l+b2l, xr2 = h1@W2r+b2r
    gemm_bias_dual<<<dim3(mb, 2, 2), 256>>>(nullptr, 2, W2l, b2l, 3, W2r, b2r, 4,
                                            N, 256, 128);
    score2_kernel<<<(Etot + 7) / 8, 256>>>(We2, att2, ea, E, Etot);
    agg2_kernel<<<N, 128>>>(bias2, E);

    // pooled softmax + sigmoid(alpha)
    final_kernel<<<1, 128>>>(alpha, out, out_size, 1.0f / (float)N);
}

// round 5
// speedup vs baseline: 1.0896x; 1.0896x over previous
#include <cuda_runtime.h>
#include <math.h>

// Problem constants (validated against in_sizes at launch).
#define NMAX 20000
#define EMAX 640000
#define ETOTMAX (EMAX + NMAX)

// ---------------- device scratch (no allocations allowed) ----------------
__device__ int   g_is64;
__device__ int   g_src[EMAX];
__device__ int   g_dst[EMAX];
__device__ float g_easum[NMAX];
__device__ float g_ealoop[NMAX];
__device__ int   g_cnt[NMAX];
__device__ int   g_cursor[NMAX];
__device__ int   g_off[NMAX + 1];
__device__ int   g_eid[ETOTMAX];
__device__ float g_xl1[NMAX * 256];
__device__ float g_xr1[NMAX * 256];
__device__ float g_h1[NMAX * 256];
__device__ float g_xl2[NMAX * 128];
__device__ float g_xr2[NMAX * 128];
__device__ float g_s1[(size_t)ETOTMAX * 8];
__device__ float g_s2[ETOTMAX];
__device__ float g_pool[128];

// Device-side scratch selector (avoids any host-side symbol queries).
__device__ __forceinline__ float* buf_sel(int code) {
    switch (code) {
        case 0:  return g_xl1;
        case 1:  return g_xr1;
        case 2:  return g_h1;
        case 3:  return g_xl2;
        default: return g_xr2;
    }
}

// ---------------- init (graph replays reuse accumulators) ----------------
__global__ void init_kernel(int n) {
    int i = blockIdx.x * blockDim.x + threadIdx.x;
    if (i < n) {
        g_easum[i]  = 0.f;
        g_cursor[i] = 0;
        g_cnt[i]    = 1;   // self-loop pre-counted
    }
    if (i < 128) g_pool[i] = 0.f;
}

// Detect whether edge_index is stored as int64 (little-endian: high words 0)
__global__ void detect_kernel(const int* __restrict__ raw) {
    int nz = 0;
    for (int i = threadIdx.x; i < 64; i += 32)
        if (raw[2 * i + 1] != 0) nz = 1;
    nz = __any_sync(0xffffffffu, nz);
    if (threadIdx.x == 0) g_is64 = nz ? 0 : 1;
}

// Extract src/dst, accumulate per-dst edge_attr sum / CSR counts
__global__ void extract_kernel(const int* __restrict__ raw,
                               const float* __restrict__ ea, int E) {
    int e = blockIdx.x * blockDim.x + threadIdx.x;
    if (e >= E) return;
    int is64 = g_is64;
    int s = is64 ? raw[2 * e]       : raw[e];
    int d = is64 ? raw[2 * (E + e)] : raw[E + e];
    g_src[e] = s;
    g_dst[e] = d;
    atomicAdd(&g_easum[d], ea[e]);
    atomicAdd(&g_cnt[d], 1);
}

__global__ void ealoop_kernel(int n) {
    int i = blockIdx.x * blockDim.x + threadIdx.x;
    if (i < n) {
        float deg = (float)(g_cnt[i] - 1);   // real incoming degree
        g_ealoop[i] = g_easum[i] / fmaxf(deg, 1.0f);
    }
}

// Single-block exclusive prefix sum over g_cnt -> g_off
__global__ void scan_kernel(int n) {
    __shared__ int sh[1024];
    __shared__ int carry;
    int tid = threadIdx.x;
    if (tid == 0) carry = 0;
    __syncthreads();
    for (int base = 0; base < n; base += 1024) {
        int i = base + tid;
        int v = (i < n) ? g_cnt[i] : 0;
        sh[tid] = v;
        __syncthreads();
        for (int o = 1; o < 1024; o <<= 1) {
            int t = (tid >= o) ? sh[tid - o] : 0;
            __syncthreads();
            sh[tid] += t;
            __syncthreads();
        }
        if (i < n) g_off[i] = carry + sh[tid] - v;
        __syncthreads();
        if (tid == 0) carry += sh[1023];
        __syncthreads();
    }
    if (tid == 0) g_off[n] = carry;
}

// Fill CSR edge-id lists (edge k<E: real edge; k>=E: self loop of node k-E)
__global__ void scatter_kernel(int E, int n) {
    int k = blockIdx.x * blockDim.x + threadIdx.x;
    int tot = E + n;
    if (k >= tot) return;
    int d = (k < E) ? g_dst[k] : (k - E);
    int pos = g_off[d] + atomicAdd(&g_cursor[d], 1);
    g_eid[pos] = k;
}

// ---- fp32 SGEMM 128x128 tile, 8x8/thread, k-panel 8, dual-weight (z) ----
__global__ void __launch_bounds__(256, 2)
gemm_bias_dual(const float* __restrict__ Ain, int Acode,
               const float* __restrict__ W0, const float* __restrict__ b0, int C0code,
               const float* __restrict__ W1, const float* __restrict__ b1, int C1code,
               int M, int K, int Nn) {
    const float* A = (Acode >= 0) ? buf_sel(Acode) : Ain;
    const float* W    = (blockIdx.z == 0) ? W0 : W1;
    const float* bias = (blockIdx.z == 0) ? b0 : b1;
    float* C = buf_sel(blockIdx.z == 0 ? C0code : C1code);

    __shared__ __align__(16) float As[8][132];   // transposed A panel, padded
    __shared__ __align__(16) float Bs[8][128];

    const int tid = threadIdx.x;
    const int tx = tid & 15, ty = tid >> 4;
    const int tm0 = ty * 8, tn0 = tx * 8;
    const int row0 = blockIdx.x * 128, col0 = blockIdx.y * 128;

    // load indices
    const int arow = tid >> 1;            // 0..127
    const int acol = (tid & 1) * 4;       // 0 or 4
    const int brow = tid >> 6;            // 0..3  (two rows per thread: +0, +4)
    const int bcol = (tid & 63) * 2;      // 0..126 step 2 -> use float2? no:
    // simpler: 256 threads load 8x128 = 1024 floats as float4: tid>>5 row, (tid&31)*4 col
    const int b_r = tid >> 5;             // 0..7
    const int b_c = (tid & 31) * 4;       // 0..124

    (void)brow; (void)bcol;

    const int a_gr = row0 + arow;
    const bool a_ok = (a_gr < M);

    float acc[8][8];
    #pragma unroll
    for (int i = 0; i < 8; i++)
        #pragma unroll
        for (int j = 0; j < 8; j++) acc[i][j] = 0.f;

    for (int k0 = 0; k0 < K; k0 += 8) {
        float4 av = make_float4(0.f, 0.f, 0.f, 0.f);
        if (a_ok) av = *(const float4*)&A[(size_t)a_gr * K + k0 + acol];
        float4 bv = *(const float4*)&W[(size_t)(k0 + b_r) * Nn + col0 + b_c];
        As[acol + 0][arow] = av.x;
        As[acol + 1][arow] = av.y;
        As[acol + 2][arow] = av.z;
        As[acol + 3][arow] = av.w;
        *(float4*)&Bs[b_r][b_c] = bv;
        __syncthreads();

        #pragma unroll
        for (int kk = 0; kk < 8; kk++) {
            float a[8], b[8];
            *(float4*)&a[0] = *(const float4*)&As[kk][tm0];
            *(float4*)&a[4] = *(const float4*)&As[kk][tm0 + 4];
            *(float4*)&b[0] = *(const float4*)&Bs[kk][tn0];
            *(float4*)&b[4] = *(const float4*)&Bs[kk][tn0 + 4];
            #pragma unroll
            for (int i = 0; i < 8; i++)
                #pragma unroll
                for (int j = 0; j < 8; j++)
                    acc[i][j] += a[i] * b[j];
        }
        __syncthreads();
    }

    // epilogue: add bias, vector stores
    float bcache[8];
    #pragma unroll
    for (int j = 0; j < 8; j++) bcache[j] = bias[col0 + tn0 + j];
    #pragma unroll
    for (int i = 0; i < 8; i++) {
        int gr = row0 + tm0 + i;
        if (gr >= M) continue;
        float4 v0 = make_float4(acc[i][0] + bcache[0], acc[i][1] + bcache[1],
                                acc[i][2] + bcache[2], acc[i][3] + bcache[3]);
        float4 v1 = make_float4(acc[i][4] + bcache[4], acc[i][5] + bcache[5],
                                acc[i][6] + bcache[6], acc[i][7] + bcache[7]);
        *(float4*)&C[(size_t)gr * Nn + col0 + tn0]     = v0;
        *(float4*)&C[(size_t)gr * Nn + col0 + tn0 + 4] = v1;
    }
}

// ---------------- layer 1 scores (H=8, C=32), one warp per CSR slot ------
__global__ void score1_kernel(const float* __restrict__ We,
                              const float* __restrict__ att,
                              const float* __restrict__ ea, int E, int Etot) {
    __shared__ float Wsh[256], Ash[256];
    int t = threadIdx.x;
    Wsh[t] = We[t];
    Ash[t] = att[t];
    __syncthreads();
    int warp = t >> 5, lane = t & 31;
    int p = blockIdx.x * 8 + warp;
    if (p >= Etot) return;
    int k = g_eid[p];
    int s, d;
    float eav;
    if (k < E) { s = g_src[k]; d = g_dst[k]; eav = ea[k]; }
    else       { s = d = k - E; eav = g_ealoop[s]; }
    const float* xl = g_xl1 + (size_t)s * 256;
    const float* xr = g_xr1 + (size_t)d * 256;
    float mine = 0.f;
    #pragma unroll
    for (int h = 0; h < 8; h++) {
        int c = h * 32 + lane;
        float m = xl[c] + xr[c] + eav * Wsh[c];
        m = (m > 0.f) ? m : 0.2f * m;
        float v = m * Ash[c];
        #pragma unroll
        for (int o = 16; o; o >>= 1) v += __shfl_xor_sync(0xffffffffu, v, o);
        if (lane == h) mine = v;
    }
    if (lane < 8) g_s1[(size_t)p * 8 + lane] = mine;
}

// ---------------- layer 2 scores (H=1, C=128) ----------------------------
__global__ void score2_kernel(const float* __restrict__ We,
                              const float* __restrict__ att,
                              const float* __restrict__ ea, int E, int Etot) {
    __shared__ float Wsh[128], Ash[128];
    int t = threadIdx.x;
    if (t < 128) { Wsh[t] = We[t]; Ash[t] = att[t]; }
    __syncthreads();
    int warp = t >> 5, lane = t & 31;
    int p = blockIdx.x * 8 + warp;
    if (p >= Etot) return;
    int k = g_eid[p];
    int s, d;
    float eav;
    if (k < E) { s = g_src[k]; d = g_dst[k]; eav = ea[k]; }
    else       { s = d = k - E; eav = g_ealoop[s]; }
    const float* xl = g_xl2 + (size_t)s * 128;
    const float* xr = g_xr2 + (size_t)d * 128;
    float acc = 0.f;
    #pragma unroll
    for (int i = 0; i < 4; i++) {
        int c = lane + 32 * i;
        float m = xl[c] + xr[c] + eav * Wsh[c];
        m = (m > 0.f) ? m : 0.2f * m;
        acc += m * Ash[c];
    }
    #pragma unroll
    for (int o = 16; o; o >>= 1) acc += __shfl_xor_sync(0xffffffffu, acc, o);
    if (lane == 0) g_s2[p] = acc;
}

// ---------- layer 1 aggregation: one block (256 thr) per node ------------
__global__ void agg1_kernel(const float* __restrict__ bias, int E) {
    const int CH = 64;
    __shared__ float mx[8], idn[8];
    __shared__ float ash[CH * 8];
    __shared__ int   ssh[CH];
    int j = blockIdx.x;
    int off = g_off[j], end = g_off[j + 1];
    int d = end - off;
    int t = threadIdx.x;
    int h = t >> 5, lane = t & 31;

    // online softmax stats per head (warp h owns head h)
    float m = -1e30f, sum = 0.f;
    for (int idx = lane; idx < d; idx += 32) {
        float sv = g_s1[(size_t)(off + idx) * 8 + h];
        if (sv > m) { sum = sum * __expf(m - sv) + 1.0f; m = sv; }
        else        { sum += __expf(sv - m); }
    }
    #pragma unroll
    for (int o = 16; o; o >>= 1) {
        float m2 = __shfl_xor_sync(0xffffffffu, m, o);
        float s2 = __shfl_xor_sync(0xffffffffu, sum, o);
        float nm = fmaxf(m, m2);
        sum = sum * __expf(m - nm) + s2 * __expf(m2 - nm);
        m = nm;
    }
    if (lane == 0) { mx[h] = m; idn[h] = 1.0f / (sum + 1e-16f); }
    __syncthreads();

    float accv = 0.f;
    for (int cs = 0; cs < d; cs += CH) {
        int cl = min(CH, d - cs);
        for (int i = t; i < cl * 8; i += 256) {
            float sv = g_s1[(size_t)(off + cs) * 8 + i];
            int hh = i & 7;
            ash[i] = __expf(sv - mx[hh]) * idn[hh];
        }
        for (int i = t; i < cl; i += 256) {
            int k = g_eid[off + cs + i];
            ssh[i] = (k < E) ? g_src[k] : (k - E);
        }
        __syncthreads();
        #pragma unroll 4
        for (int el = 0; el < cl; el++) {
            float a = ash[el * 8 + h];
            accv += a * g_xl1[(size_t)ssh[el] * 256 + h * 32 + lane];
        }
        __syncthreads();
    }
    int c = h * 32 + lane;
    g_h1[(size_t)j * 256 + c] = fmaxf(accv + bias[c], 0.f);
}

// ---------- layer 2 aggregation + mean pool: block (128 thr) per node ----
__global__ void agg2_kernel(const float* __restrict__ bias, int E) {
    __shared__ float wm[4], ws[4];
    __shared__ float M0sh, IVsh;
    __shared__ float ash[128];
    __shared__ int   ssh[128];
    int j = blockIdx.x;
    int off = g_off[j], end = g_off[j + 1];
    int d = end - off;
    int t = threadIdx.x;
    int w = t >> 5, lane = t & 31;

    float m = -1e30f, sum = 0.f;
    for (int idx = t; idx < d; idx += 128) {
        float sv = g_s2[off + idx];
        if (sv > m) { sum = sum * __expf(m - sv) + 1.0f; m = sv; }
        else        { sum += __expf(sv - m); }
    }
    #pragma unroll
    for (int o = 16; o; o >>= 1) {
        float m2 = __shfl_xor_sync(0xffffffffu, m, o);
        float s2 = __shfl_xor_sync(0xffffffffu, sum, o);
        float nm = fmaxf(m, m2);
        sum = sum * __expf(m - nm) + s2 * __expf(m2 - nm);
        m = nm;
    }
    if (lane == 0) { wm[w] = m; ws[w] = sum; }
    __syncthreads();
    if (t == 0) {
        float M0 = fmaxf(fmaxf(wm[0], wm[1]), fmaxf(wm[2], wm[3]));
        float S0 = ws[0] * __expf(wm[0] - M0) + ws[1] * __expf(wm[1] - M0)
                 + ws[2] * __expf(wm[2] - M0) + ws[3] * __expf(wm[3] - M0);
        M0sh = M0;
        IVsh = 1.0f / (S0 + 1e-16f);
    }
    __syncthreads();
    float M0 = M0sh, invd = IVsh;

    float accv = 0.f;
    for (int cs = 0; cs < d; cs += 128) {
        int cl = min(128, d - cs);
        if (t < cl) {
            ash[t] = __expf(g_s2[off + cs + t] - M0) * invd;
            int k = g_eid[off + cs + t];
            ssh[t] = (k < E) ? g_src[k] : (k - E);
        }
        __syncthreads();
        #pragma unroll 4
        for (int el = 0; el < cl; el++)
            accv += ash[el] * g_xl2[(size_t)ssh[el] * 128 + t];
        __syncthreads();
    }
    float val = fmaxf(accv + bias[t], 0.f);
    atomicAdd(&g_pool[t], val);
}

// ---------------- final: mean, softmax, sigmoid(alpha) -------------------
__global__ void final_kernel(const float* __restrict__ alpha_in,
                             float* __restrict__ out, int out_size, float invN) {
    __shared__ float sh[128];
    int t = threadIdx.x;
    float v = g_pool[t] * invN;
    sh[t] = v;
    __syncthreads();
    for (int o = 64; o; o >>= 1) {
        if (t < o) sh[t] = fmaxf(sh[t], sh[t + o]);
        __syncthreads();
    }
    float mx = sh[0];
    __syncthreads();
    float e = __expf(v - mx);
    sh[t] = e;
    __syncthreads();
    for (int o = 64; o; o >>= 1) {
        if (t < o) sh[t] += sh[t + o];
        __syncthreads();
    }
    float s = sh[0];
    out[t] = e / s;
    if (t == 0 && out_size > 128)
        out[128] = 1.0f / (1.0f + __expf(-alpha_in[0]));
}

// -------------------------------------------------------------------------
extern "C" void kernel_launch(void* const* d_in, const int* in_sizes, int n_in,
                              void* d_out, int out_size) {
    (void)n_in;
    const float* x     = (const float*)d_in[0];
    const int*   eidx  = (const int*)d_in[1];   // int32 or int64 (detected)
    const float* ea    = (const float*)d_in[2];
    const float* W1l   = (const float*)d_in[3];
    const float* b1l   = (const float*)d_in[4];
    const float* W1r   = (const float*)d_in[5];
    const float* b1r   = (const float*)d_in[6];
    const float* We1   = (const float*)d_in[7];
    const float* att1  = (const float*)d_in[8];
    const float* bias1 = (const float*)d_in[9];
    const float* W2l   = (const float*)d_in[10];
    const float* b2l   = (const float*)d_in[11];
    const float* W2r   = (const float*)d_in[12];
    const float* b2r   = (const float*)d_in[13];
    const float* We2   = (const float*)d_in[14];
    const float* att2  = (const float*)d_in[15];
    const float* bias2 = (const float*)d_in[16];
    const float* alpha = (const float*)d_in[17];
    float* out = (float*)d_out;

    int N = in_sizes[0] / 128;
    if (N > NMAX) N = NMAX;
    int E = in_sizes[1] / 2;
    if (E > EMAX) E = EMAX;
    int Etot = E + N;

    // graph preprocessing
    init_kernel<<<(N + 255) / 256, 256>>>(N);
    detect_kernel<<<1, 32>>>(eidx);
    extract_kernel<<<(E + 255) / 256, 256>>>(eidx, ea, E);
    ealoop_kernel<<<(N + 255) / 256, 256>>>(N);
    scan_kernel<<<1, 1024>>>(N);
    scatter_kernel<<<(Etot + 255) / 256, 256>>>(E, N);

    int mb = (N + 127) / 128;

    // layer 1: xl1 = x@W1l+b1l, xr1 = x@W1r+b1r (one dual launch)
    gemm_bias_dual<<<dim3(mb, 2, 2), 256>>>(x, -1, W1l, b1l, 0, W1r, b1r, 1,
                                            N, 128, 256);
    score1_kernel<<<(Etot + 7) / 8, 256>>>(We1, att1, ea, E, Etot);
    agg1_kernel<<<N, 256>>>(bias1, E);

    // layer 2: xl2 = h1@W2l+b2l, xr2 = h1@W2r+b2r
    gemm_bias_dual<<<dim3(mb, 1, 2), 256>>>(nullptr, 2, W2l, b2l, 3, W2r, b2r, 4,
                                            N, 256, 128);
    score2_kernel<<<(Etot + 7) / 8, 256>>>(We2, att2, ea, E, Etot);
    agg2_kernel<<<N, 128>>>(bias2, E);

    // pooled softmax + sigmoid(alpha)
    final_kernel<<<1, 128>>>(alpha, out, out_size, 1.0f / (float)N);
}